// round 15
// baseline (speedup 1.0000x reference)
#include <cuda_runtime.h>
#include <cuda_fp16.h>
#include <cstdint>
#include <math.h>

#define HEADS 16
#define HEAD_DIM 64

// ---------------------------------------------------------------------------
// Scratch (fp16 hi/lo split pipeline)
// ---------------------------------------------------------------------------
__device__ __align__(16) __half g_xhi[4096 * 1024];
__device__ __align__(16) __half g_xlo[4096 * 1024];
__device__ __align__(16) __half g_bhi[3072 * 1024];
__device__ __align__(16) __half g_blo[3072 * 1024];
__device__ __align__(16) __half g_qkhi[4096 * 2048];   // [BL][2D] q|k
__device__ __align__(16) __half g_qklo[4096 * 2048];   // lo used for q only
__device__ __align__(16) __half g_vthi[2048 * 2048];   // [B*H*64][L]
__device__ __align__(16) __half g_aohi[4096 * 1024];

// ---------------------------------------------------------------------------
// PTX helpers (base sm_103 ISA only)
// ---------------------------------------------------------------------------
__device__ __forceinline__ uint32_t smem_u32(const void* p) {
    uint32_t a;
    asm("{ .reg .u64 t; cvta.to.shared.u64 t, %1; cvt.u32.u64 %0, t; }" : "=r"(a) : "l"(p));
    return a;
}
__device__ __forceinline__ void cp_async16(uint32_t saddr, const void* gaddr) {
    asm volatile("cp.async.cg.shared.global [%0], [%1], 16;" :: "r"(saddr), "l"(gaddr));
}
#define CP_COMMIT() asm volatile("cp.async.commit_group;" ::: "memory")
#define CP_WAIT(n)  asm volatile("cp.async.wait_group %0;" :: "n"(n) : "memory")

__device__ __forceinline__ void ldm_x4(uint32_t& r0, uint32_t& r1, uint32_t& r2, uint32_t& r3, uint32_t a) {
    asm volatile("ldmatrix.sync.aligned.m8n8.x4.shared.b16 {%0,%1,%2,%3}, [%4];"
                 : "=r"(r0), "=r"(r1), "=r"(r2), "=r"(r3) : "r"(a));
}
__device__ __forceinline__ void mma_f32(float* c, const uint32_t* a, const uint32_t* b) {
    asm volatile("mma.sync.aligned.m16n8k16.row.col.f32.f16.f16.f32 "
                 "{%0,%1,%2,%3}, {%4,%5,%6,%7}, {%8,%9}, {%0,%1,%2,%3};"
                 : "+f"(c[0]), "+f"(c[1]), "+f"(c[2]), "+f"(c[3])
                 : "r"(a[0]), "r"(a[1]), "r"(a[2]), "r"(a[3]), "r"(b[0]), "r"(b[1]));
}
__device__ __forceinline__ void mma_f16(uint32_t* c, const uint32_t* a, const uint32_t* b) {
    asm volatile("mma.sync.aligned.m16n8k16.row.col.f16.f16.f16.f16 "
                 "{%0,%1}, {%2,%3,%4,%5}, {%6,%7}, {%0,%1};"
                 : "+r"(c[0]), "+r"(c[1])
                 : "r"(a[0]), "r"(a[1]), "r"(a[2]), "r"(a[3]), "r"(b[0]), "r"(b[1]));
}
__device__ __forceinline__ void merge_f16acc(float* c, const uint32_t* cx) {
    float2 v0 = __half22float2(*reinterpret_cast<const __half2*>(&cx[0]));
    float2 v1 = __half22float2(*reinterpret_cast<const __half2*>(&cx[1]));
    c[0] += v0.x; c[1] += v0.y; c[2] += v1.x; c[3] += v1.y;
}
__device__ __forceinline__ float ex2f(float x) {
    float y; asm("ex2.approx.f32 %0, %1;" : "=f"(y) : "f"(x)); return y;
}
__device__ __forceinline__ uint32_t pack_h2(float x, float y) {
    uint32_t h;
    asm("cvt.rn.f16x2.f32 %0, %1, %2;" : "=r"(h) : "f"(y), "f"(x));
    return h;
}
__device__ __forceinline__ void split2h(float x, float y, uint32_t& hi2, uint32_t& lo2) {
    uint32_t h = pack_h2(x, y);
    float2 hf = __half22float2(*reinterpret_cast<__half2*>(&h));
    lo2 = pack_h2(x - hf.x, y - hf.y);
    hi2 = h;
}

#define Q_SCALE 0.18033688011112042f   /* 0.125 * log2(e), folded into q */

// ---------------------------------------------------------------------------
// split kernels
// ---------------------------------------------------------------------------
__global__ __launch_bounds__(256) void split_rows(
    const float* __restrict__ in, __half* __restrict__ hi,
    __half* __restrict__ lo, int n4)
{
    int i = blockIdx.x * blockDim.x + threadIdx.x;
    if (i >= n4) return;
    float4 v = ((const float4*)in)[i];
    uint32_t h0, l0, h1, l1;
    split2h(v.x, v.y, h0, l0);
    split2h(v.z, v.w, h1, l1);
    ((uint32_t*)hi)[2 * i + 0] = h0; ((uint32_t*)hi)[2 * i + 1] = h1;
    ((uint32_t*)lo)[2 * i + 0] = l0; ((uint32_t*)lo)[2 * i + 1] = l1;
}

__global__ __launch_bounds__(256) void split_transpose(
    const float* __restrict__ w, __half* __restrict__ th,
    __half* __restrict__ tl, int K, int N)
{
    __shared__ float tile[32][33];
    int n0 = blockIdx.x * 32, k0 = blockIdx.y * 32;
    int tx = threadIdx.x, ty = threadIdx.y;  // (32, 8)
#pragma unroll
    for (int r = 0; r < 32; r += 8)
        tile[ty + r][tx] = w[(size_t)(k0 + ty + r) * N + n0 + tx];
    __syncthreads();
#pragma unroll
    for (int r = 0; r < 32; r += 8) {
        float v = tile[tx][ty + r];
        __half h = __float2half_rn(v);
        th[(size_t)(n0 + ty + r) * K + k0 + tx] = h;
        tl[(size_t)(n0 + ty + r) * K + k0 + tx] = __float2half_rn(v - __half2float(h));
    }
}

// ---------------------------------------------------------------------------
// HMMA GEMM mainloop — R11 config (proven fastest): CTA = 128 thr, tile
// 128x64, warps 2x2 (64x32 each), KC=32, 2-stage cp.async, 3 CTAs/SM.
// ---------------------------------------------------------------------------
#define KC 32
#define TILE_A (128 * 80u)
#define TILE_BT (64 * 80u)
#define STAGE_B (2 * TILE_A + 2 * TILE_BT)   // 30720 B; 2 stages = 61440 B

#define GEMM_MAINLOOP(Ahi, Alo, Bhi, Blo, Kdim, cacc, cx, LOADAL, LOADBL, DOAL, DOBL)    \
    extern __shared__ __align__(16) char dsm[];                                          \
    const uint32_t sbase = smem_u32(dsm);                                                \
    const int tid = threadIdx.x;                                                         \
    const int lane = tid & 31, wid = tid >> 5;                                           \
    const int wm = (wid >> 1) * 64;                                                      \
    const int wn = (wid & 1) * 32;                                                       \
    float cacc[4][4][4];                                                                 \
    uint32_t cx[4][4][2];                                                                \
    _Pragma("unroll") for (int i = 0; i < 4; i++)                                        \
    _Pragma("unroll") for (int j = 0; j < 4; j++) {                                      \
        _Pragma("unroll") for (int e = 0; e < 4; e++) cacc[i][j][e] = 0.0f;              \
        cx[i][j][0] = 0u; cx[i][j][1] = 0u;                                              \
    }                                                                                    \
    const int lrow = tid >> 2;                                                           \
    const int lcu  = tid & 3;                                                            \
    auto load_chunk = [&](int stage, int k0) {                                           \
        const uint32_t st = sbase + (uint32_t)stage * STAGE_B;                           \
        _Pragma("unroll") for (int i = 0; i < 4; i++) {                                  \
            int row = lrow + i * 32;                                                     \
            cp_async16(st + (uint32_t)(row * 80 + lcu * 16),                             \
                       (Ahi) + (size_t)(bm + row) * Kdim + k0 + lcu * 8);                \
        }                                                                                \
        if (LOADAL) {                                                                    \
            _Pragma("unroll") for (int i = 0; i < 4; i++) {                              \
                int row = lrow + i * 32;                                                 \
                cp_async16(st + TILE_A + (uint32_t)(row * 80 + lcu * 16),                \
                           (Alo) + (size_t)(bm + row) * Kdim + k0 + lcu * 8);            \
            }                                                                            \
        }                                                                                \
        _Pragma("unroll") for (int i = 0; i < 2; i++) {                                  \
            int row = lrow + i * 32;                                                     \
            cp_async16(st + 2 * TILE_A + (uint32_t)(row * 80 + lcu * 16),                \
                       (Bhi) + (size_t)(bn + row) * Kdim + k0 + lcu * 8);                \
        }                                                                                \
        if (LOADBL) {                                                                    \
            _Pragma("unroll") for (int i = 0; i < 2; i++) {                              \
                int row = lrow + i * 32;                                                 \
                cp_async16(st + 2 * TILE_A + TILE_BT + (uint32_t)(row * 80 + lcu * 16),  \
                           (Blo) + (size_t)(bn + row) * Kdim + k0 + lcu * 8);            \
            }                                                                            \
        }                                                                                \
        CP_COMMIT();                                                                     \
    };                                                                                   \
    const uint32_t aoff  = (uint32_t)((lane & 15) * 80 + (lane >> 4) * 16);              \
    const uint32_t boff4 = (uint32_t)((lane & 7) * 80 + ((lane >> 3) & 1) * 16           \
                                      + (lane >> 4) * 640);                              \
    const int nchunk = Kdim / KC;                                                        \
    load_chunk(0, 0);                                                                    \
    for (int ch = 0; ch < nchunk; ch++) {                                                \
        if (ch + 1 < nchunk) { load_chunk((ch + 1) & 1, (ch + 1) * KC); CP_WAIT(1); }    \
        else                 { CP_WAIT(0); }                                             \
        __syncthreads();                                                                 \
        const uint32_t st = sbase + (uint32_t)(ch & 1) * STAGE_B;                        \
        const uint32_t sAhi = st + (uint32_t)(wm * 80);                                  \
        const uint32_t sAlo = st + TILE_A + (uint32_t)(wm * 80);                         \
        const uint32_t sBhi = st + 2 * TILE_A + (uint32_t)(wn * 80);                     \
        const uint32_t sBlo = st + 2 * TILE_A + TILE_BT + (uint32_t)(wn * 80);           \
        _Pragma("unroll") for (int kk = 0; kk < KC; kk += 16) {                          \
            uint32_t ah[4][4], al[4][4], bh[4][2], bl[4][2];                             \
            _Pragma("unroll") for (int mi = 0; mi < 4; mi++) {                           \
                uint32_t abase = (uint32_t)(mi * 16 * 80 + kk * 2) + aoff;               \
                ldm_x4(ah[mi][0], ah[mi][1], ah[mi][2], ah[mi][3], sAhi + abase);        \
                if (DOAL) ldm_x4(al[mi][0], al[mi][1], al[mi][2], al[mi][3], sAlo + abase);\
            }                                                                            \
            _Pragma("unroll") for (int np = 0; np < 4; np += 2) {                        \
                uint32_t bbase = (uint32_t)(np * 8 * 80 + kk * 2) + boff4;               \
                ldm_x4(bh[np][0], bh[np][1], bh[np + 1][0], bh[np + 1][1], sBhi + bbase);\
                if (DOBL) ldm_x4(bl[np][0], bl[np][1], bl[np + 1][0], bl[np + 1][1], sBlo + bbase);\
            }                                                                            \
            _Pragma("unroll") for (int mi = 0; mi < 4; mi++)                             \
            _Pragma("unroll") for (int ni = 0; ni < 4; ni++)                             \
                mma_f32(cacc[mi][ni], ah[mi], bh[ni]);                                   \
            if (DOBL) {                                                                  \
                _Pragma("unroll") for (int mi = 0; mi < 4; mi++)                         \
                _Pragma("unroll") for (int ni = 0; ni < 4; ni++)                         \
                    mma_f16(cx[mi][ni], ah[mi], bl[ni]);                                 \
            }                                                                            \
            if (DOAL) {                                                                  \
                _Pragma("unroll") for (int mi = 0; mi < 4; mi++)                         \
                _Pragma("unroll") for (int ni = 0; ni < 4; ni++)                         \
                    mma_f16(cx[mi][ni], al[mi], bh[ni]);                                 \
            }                                                                            \
        }                                                                                \
        __syncthreads();                                                                 \
    }                                                                                    \
    _Pragma("unroll") for (int mi = 0; mi < 4; mi++)                                     \
    _Pragma("unroll") for (int ni = 0; ni < 4; ni++)                                     \
        merge_f16acc(cacc[mi][ni], cx[mi][ni]);

// GEMM variant 1: output projection. A = fp16 O (hi only), B split. 2-pass.
__global__ __launch_bounds__(128, 3) void gemm_proj(
    const __half* __restrict__ Ahi,
    const __half* __restrict__ Bhi, const __half* __restrict__ Blo,
    float* __restrict__ C, int N, int K)
{
    const int bm = blockIdx.y * 128, bn = blockIdx.x * 64;
    GEMM_MAINLOOP(Ahi, Ahi, Bhi, Blo, K, c, cxx, false, true, false, true)
#pragma unroll
    for (int mi = 0; mi < 4; mi++) {
        const int r0 = bm + wm + mi * 16 + (lane >> 2);
#pragma unroll
        for (int ni = 0; ni < 4; ni++) {
            const int col = bn + wn + ni * 8 + (lane & 3) * 2;
            *(float2*)(C + (size_t)r0 * N + col)       = make_float2(c[mi][ni][0], c[mi][ni][1]);
            *(float2*)(C + (size_t)(r0 + 8) * N + col) = make_float2(c[mi][ni][2], c[mi][ni][3]);
        }
    }
}

// GEMM variant 2: qkv. Q tiles 3-pass (q split hi/lo); K tiles 2-pass; V 1-pass.
__global__ __launch_bounds__(128, 3) void gemm_qkv(
    const __half* __restrict__ Ahi, const __half* __restrict__ Alo,
    const __half* __restrict__ Bhi, const __half* __restrict__ Blo,
    __half* __restrict__ qkhi, __half* __restrict__ qklo,
    __half* __restrict__ vthi,
    int K, int L, int Dq)
{
    const int bm = blockIdx.y * 128, bn = blockIdx.x * 64;
    const int D2 = 2 * Dq;
    const bool doA = (bn < Dq);
    const bool doB = (bn < D2);
    GEMM_MAINLOOP(Ahi, Alo, Bhi, Blo, K, c, cxx, doA, doB, doA, doB)
#pragma unroll
    for (int mi = 0; mi < 4; mi++) {
#pragma unroll
        for (int ni = 0; ni < 4; ni++) {
            const int col = bn + wn + ni * 8 + (lane & 3) * 2;
            const float sc = (col < Dq) ? Q_SCALE : 1.0f;
#pragma unroll
            for (int half = 0; half < 2; half++) {
                const int row = bm + wm + mi * 16 + (lane >> 2) + half * 8;
                float x = c[mi][ni][2 * half] * sc, y = c[mi][ni][2 * half + 1] * sc;
                if (col < Dq) {                     // q: hi + lo
                    uint32_t hi2, lo2;
                    split2h(x, y, hi2, lo2);
                    *(uint32_t*)(qkhi + (size_t)row * D2 + col) = hi2;
                    *(uint32_t*)(qklo + (size_t)row * D2 + col) = lo2;
                } else if (col < D2) {              // k: hi only
                    *(uint32_t*)(qkhi + (size_t)row * D2 + col) = pack_h2(x, y);
                } else {                            // v: transposed fp16
                    uint32_t hi2 = pack_h2(x, y);
                    int cc = col - D2, hh = cc >> 6, dd = cc & 63;
                    int bb = row / L, ll = row % L;
                    size_t base = ((size_t)((bb * HEADS + hh) * 64 + dd)) * L + ll;
                    ((unsigned short*)vthi)[base]     = (unsigned short)(hi2 & 0xFFFF);
                    ((unsigned short*)vthi)[base + L] = (unsigned short)(hi2 >> 16);
                }
            }
        }
    }
}

// ---------------------------------------------------------------------------
// Tensor-core flash attention (causal), FA2-style intra-warp pipelining:
// each iteration issues QK(t+1) and PV(t) MMAs back-to-back (independent),
// then runs softmax(t+1) while the tensor pipe drains. CTA = 128 thr,
// Q-tile 64, K-tile 64, 3-stage KV ring + persistent Q-lo smem, 2 CTAs/SM.
// QK^T 2-pass (qh*kh f32 + ql*kh f16); PV single fp16 pass; O fp16.
// ---------------------------------------------------------------------------
#define KSTR 144u
#define ATT_STG 18432u
#define QLO_B 9216u

__global__ __launch_bounds__(128, 2) void attn_mma(
    const __half* __restrict__ qkhi, const __half* __restrict__ qklo,
    const __half* __restrict__ vthi,
    __half* __restrict__ aohi,
    int L, int Dq)
{
    extern __shared__ __align__(16) char dsm[];
    const uint32_t sb = smem_u32(dsm);          // Q-lo region
    const uint32_t stg = sb + QLO_B;            // KV stage ring base
    const int h = blockIdx.y, b = blockIdx.z;
    const int qblk = gridDim.x - 1 - blockIdx.x;     // heavy first
    const int qlo = qblk * 64;
    const int tid = threadIdx.x, lane = tid & 31, w = tid >> 5;
    const int D2 = 2 * Dq;

    // ---- Q tile: hi -> stage0 (transient), lo -> persistent QLO region ----
#pragma unroll
    for (int i = 0; i < 8; i++) {
        int idx = tid + i * 128;
        int arr = idx >> 9;                      // 0 = Q-hi, 1 = Q-lo
        int r = (idx >> 3) & 63;
        int u = idx & 7;
        const __half* g = (arr ? qklo : qkhi) +
            (size_t)(b * L + qlo + r) * D2 + h * HEAD_DIM + u * 8;
        uint32_t dst = (arr ? sb : stg) + (uint32_t)r * KSTR + u * 16;
        cp_async16(dst, g);
    }
    CP_COMMIT();
    CP_WAIT(0);
    __syncthreads();

    uint32_t aQh[4][4];
    const uint32_t aoff = (uint32_t)((lane & 15) * KSTR + (lane >> 4) * 16);
#pragma unroll
    for (int g = 0; g < 4; g++) {
        uint32_t base = stg + (uint32_t)(w * 16) * KSTR + g * 32 + aoff;
        ldm_x4(aQh[g][0], aQh[g][1], aQh[g][2], aQh[g][3], base);
    }
    __syncthreads();   // Q-hi consumed; stage0 free. Q-lo stays in smem.
    const uint32_t qlbase = sb + (uint32_t)(w * 16) * KSTR + aoff;

    float cO[8][4];
#pragma unroll
    for (int n = 0; n < 8; n++)
#pragma unroll
        for (int e = 0; e < 4; e++) cO[n][e] = 0.0f;
    float m0 = -1e30f, m1 = -1e30f, ls0 = 0.0f, ls1 = 0.0f;
    float f0 = 1.0f, f1 = 1.0f;
    uint32_t pk[8][2];
    float cS[8][4];
    uint32_t cSx[8][2];

    const int nt = qblk + 1;
    auto loadKV = [&](int s, int kb) {
        const uint32_t st = stg + (uint32_t)s * ATT_STG;
#pragma unroll
        for (int i = 0; i < 8; i++) {
            int idx = tid + i * 128;
            int arr = idx >> 9;                  // 0 = K-hi, 1 = V-hi
            int r = (idx >> 3) & 63;
            int u = idx & 7;
            const __half* g;
            if (arr == 0)
                g = qkhi + (size_t)(b * L + kb + r) * D2 + Dq + h * HEAD_DIM + u * 8;
            else
                g = vthi + (size_t)((b * HEADS + h) * HEAD_DIM + r) * L + kb + u * 8;
            cp_async16(st + (uint32_t)arr * 9216u + (uint32_t)r * KSTR + u * 16, g);
        }
        CP_COMMIT();
    };

    const uint32_t boff4 = (uint32_t)((lane & 7) * KSTR + ((lane >> 3) & 1) * 16
                                      + (lane >> 4) * (8 * KSTR));
    const int r0 = qlo + w * 16 + (lane >> 2);
    const int colb = 2 * (lane & 3);

    // QK for tile `tile` (stage tile%3): qh*kh f32 + ql*kh f16, then merge.
    auto qk_tile = [&](int tile) {
        const uint32_t st = stg + (uint32_t)(tile % 3) * ATT_STG;
#pragma unroll
        for (int t8 = 0; t8 < 8; t8++) {
#pragma unroll
            for (int e = 0; e < 4; e++) cS[t8][e] = 0.0f;
            cSx[t8][0] = 0u; cSx[t8][1] = 0u;
        }
#pragma unroll
        for (int g = 0; g < 4; g++) {
            uint32_t ql[4];
            ldm_x4(ql[0], ql[1], ql[2], ql[3], qlbase + g * 32);
#pragma unroll
            for (int t8 = 0; t8 < 8; t8 += 2) {
                uint32_t kaddr = st + (uint32_t)(t8 * 8) * KSTR + g * 32 + boff4;
                uint32_t kh[4];
                ldm_x4(kh[0], kh[1], kh[2], kh[3], kaddr);
                mma_f32(cS[t8],     aQh[g], kh + 0);
                mma_f32(cS[t8 + 1], aQh[g], kh + 2);
                mma_f16(cSx[t8],     ql, kh + 0);
                mma_f16(cSx[t8 + 1], ql, kh + 2);
            }
        }
    };

    // softmax for tile `tile`: produces pk, f0/f1; updates m, ls.
    auto softmax_tile = [&](int tile) {
        const int kb = tile * 64;
#pragma unroll
        for (int t8 = 0; t8 < 8; t8++) merge_f16acc(cS[t8], cSx[t8]);
        float mt0 = -1e30f, mt1 = -1e30f;
        const bool maskT = (kb + 63) > (qlo + w * 16);
        if (maskT) {
#pragma unroll
            for (int t8 = 0; t8 < 8; t8++) {
                const int c0 = kb + 8 * t8 + colb;
#pragma unroll
                for (int e = 0; e < 4; e++) {
                    float s = cS[t8][e];
                    int col = c0 + (e & 1);
                    int row = (e < 2) ? r0 : (r0 + 8);
                    if (col > row) s = -1e30f;
                    cS[t8][e] = s;
                    if (e < 2) mt0 = fmaxf(mt0, s); else mt1 = fmaxf(mt1, s);
                }
            }
        } else {
#pragma unroll
            for (int t8 = 0; t8 < 8; t8++) {
                mt0 = fmaxf(mt0, fmaxf(cS[t8][0], cS[t8][1]));
                mt1 = fmaxf(mt1, fmaxf(cS[t8][2], cS[t8][3]));
            }
        }
        mt0 = fmaxf(mt0, __shfl_xor_sync(0xffffffffu, mt0, 1));
        mt0 = fmaxf(mt0, __shfl_xor_sync(0xffffffffu, mt0, 2));
        mt1 = fmaxf(mt1, __shfl_xor_sync(0xffffffffu, mt1, 1));
        mt1 = fmaxf(mt1, __shfl_xor_sync(0xffffffffu, mt1, 2));
        const float mn0 = fmaxf(m0, mt0), mn1 = fmaxf(m1, mt1);
        f0 = ex2f(m0 - mn0); f1 = ex2f(m1 - mn1);
        m0 = mn0; m1 = mn1;
        float ps0 = 0.0f, ps1 = 0.0f;
#pragma unroll
        for (int t8 = 0; t8 < 8; t8++) {
            float p0 = ex2f(cS[t8][0] - mn0);
            float p1 = ex2f(cS[t8][1] - mn0);
            float p2 = ex2f(cS[t8][2] - mn1);
            float p3 = ex2f(cS[t8][3] - mn1);
            ps0 += p0 + p1; ps1 += p2 + p3;
            pk[t8][0] = pack_h2(p0, p1);
            pk[t8][1] = pack_h2(p2, p3);
        }
        ls0 = ls0 * f0 + ps0;
        ls1 = ls1 * f1 + ps1;
    };

    // PV for tile `tile` (stage tile%3): rescale cO by f, accumulate P*V.
    auto pv_tile = [&](int tile) {
        const uint32_t st = stg + (uint32_t)(tile % 3) * ATT_STG;
#pragma unroll
        for (int n = 0; n < 8; n++) {
            cO[n][0] *= f0; cO[n][1] *= f0; cO[n][2] *= f1; cO[n][3] *= f1;
        }
#pragma unroll
        for (int g = 0; g < 4; g++) {
            uint32_t a[4] = { pk[2 * g][0], pk[2 * g][1], pk[2 * g + 1][0], pk[2 * g + 1][1] };
#pragma unroll
            for (int n = 0; n < 8; n += 2) {
                uint32_t vaddr = st + 9216u + (uint32_t)(n * 8) * KSTR + g * 32 + boff4;
                uint32_t vh[4];
                ldm_x4(vh[0], vh[1], vh[2], vh[3], vaddr);
                mma_f32(cO[n],     a, vh + 0);
                mma_f32(cO[n + 1], a, vh + 2);
            }
        }
    };

    // ---- pipelined mainloop ----
    loadKV(0, 0);
    if (nt > 1) { loadKV(1, 64); CP_WAIT(1); } else { CP_WAIT(0); }
    __syncthreads();
    qk_tile(0);
    softmax_tile(0);

    for (int t = 0; t < nt; t++) {
        if (t + 2 < nt) { loadKV((t + 2) % 3, (t + 2) * 64); CP_WAIT(1); }
        else            { CP_WAIT(0); }
        __syncthreads();

        if (t + 1 < nt) qk_tile(t + 1);   // independent MMAs queued first
        pv_tile(t);                       // PV(t) fills the pipe too
        if (t + 1 < nt) softmax_tile(t + 1);  // serial chain overlapped
        __syncthreads();
    }

    // ---- epilogue: normalize, store fp16 ----
    float l0 = ls0;
    l0 += __shfl_xor_sync(0xffffffffu, l0, 1);
    l0 += __shfl_xor_sync(0xffffffffu, l0, 2);
    float l1 = ls1;
    l1 += __shfl_xor_sync(0xffffffffu, l1, 1);
    l1 += __shfl_xor_sync(0xffffffffu, l1, 2);
    const float i0 = 1.0f / l0, i1 = 1.0f / l1;

    const size_t o0 = (size_t)(b * L + r0) * Dq + h * HEAD_DIM;
    const size_t o1 = o0 + (size_t)8 * Dq;
#pragma unroll
    for (int n = 0; n < 8; n++) {
        *(uint32_t*)(aohi + o0 + n * 8 + colb) = pack_h2(cO[n][0] * i0, cO[n][1] * i0);
        *(uint32_t*)(aohi + o1 + n * 8 + colb) = pack_h2(cO[n][2] * i1, cO[n][3] * i1);
    }
}

// ---------------------------------------------------------------------------
// Launch
// ---------------------------------------------------------------------------
extern "C" void kernel_launch(void* const* d_in, const int* in_sizes, int n_in,
                              void* d_out, int out_size)
{
    const float* x      = (const float*)d_in[0];
    const float* w_qkv  = (const float*)d_in[1];
    const float* w_proj = (const float*)d_in[2];
    float* out = (float*)d_out;

    int D  = (int)(sqrt((double)in_sizes[2]) + 0.5);
    int BL = in_sizes[0] / D;
    int L  = 2048;
    if (BL < L) L = BL;
    int Bb = BL / L;

    __half *xhi, *xlo, *bhi, *blo, *qkhi, *qklo, *vthi, *aohi;
    cudaGetSymbolAddress((void**)&xhi, g_xhi);
    cudaGetSymbolAddress((void**)&xlo, g_xlo);
    cudaGetSymbolAddress((void**)&bhi, g_bhi);
    cudaGetSymbolAddress((void**)&blo, g_blo);
    cudaGetSymbolAddress((void**)&qkhi, g_qkhi);
    cudaGetSymbolAddress((void**)&qklo, g_qklo);
    cudaGetSymbolAddress((void**)&vthi, g_vthi);
    cudaGetSymbolAddress((void**)&aohi, g_aohi);

    const int gemmSmem = (int)(2 * STAGE_B);           // 61440 B -> 3 CTAs/SM
    const int attnSmem = (int)(QLO_B + 3 * ATT_STG);   // 64512 B -> 2 CTAs/SM
    cudaFuncSetAttribute(gemm_proj, cudaFuncAttributeMaxDynamicSharedMemorySize, gemmSmem);
    cudaFuncSetAttribute(gemm_qkv,  cudaFuncAttributeMaxDynamicSharedMemorySize, gemmSmem);
    cudaFuncSetAttribute(attn_mma,  cudaFuncAttributeMaxDynamicSharedMemorySize, attnSmem);

    // 1) qkv projection -> q(scaled) hi+lo, k hi, v transposed fp16
    split_rows<<<(BL * D / 4 + 255) / 256, 256>>>(x, xhi, xlo, BL * D / 4);
    split_transpose<<<dim3(3 * D / 32, D / 32), dim3(32, 8)>>>(w_qkv, bhi, blo, D, 3 * D);
    gemm_qkv<<<dim3(3 * D / 64, BL / 128), 128, gemmSmem>>>(
        xhi, xlo, bhi, blo, qkhi, qklo, vthi, D, L, D);

    // 2) tensor-core flash attention -> fp16 O
    attn_mma<<<dim3(L / 64, HEADS, Bb), 128, attnSmem>>>(
        qkhi, qklo, vthi, aohi, L, D);

    // 3) output projection (2-pass) -> fp32
    split_transpose<<<dim3(D / 32, D / 32), dim3(32, 8)>>>(w_proj, bhi, blo, D, D);
    gemm_proj<<<dim3(D / 64, BL / 128), 128, gemmSmem>>>(
        aohi, bhi, blo, out, D, D);
}

// round 17
// speedup vs baseline: 1.0578x; 1.0578x over previous
#include <cuda_runtime.h>
#include <cuda_fp16.h>
#include <cstdint>
#include <math.h>

#define HEADS 16
#define HEAD_DIM 64

// ---------------------------------------------------------------------------
// Scratch (fp16 hi/lo split pipeline)
// ---------------------------------------------------------------------------
__device__ __align__(16) __half g_xhi[4096 * 1024];
__device__ __align__(16) __half g_xlo[4096 * 1024];
__device__ __align__(16) __half g_bhi[3072 * 1024];
__device__ __align__(16) __half g_blo[3072 * 1024];
__device__ __align__(16) __half g_qkhi[4096 * 2048];   // [BL][2D] q|k
__device__ __align__(16) __half g_qklo[4096 * 2048];   // lo used for q only
__device__ __align__(16) __half g_vthi[2048 * 2048];   // [B*H*64][L]
__device__ __align__(16) __half g_aohi[4096 * 1024];

// ---------------------------------------------------------------------------
// PTX helpers (base sm_103 ISA only)
// ---------------------------------------------------------------------------
__device__ __forceinline__ uint32_t smem_u32(const void* p) {
    uint32_t a;
    asm("{ .reg .u64 t; cvta.to.shared.u64 t, %1; cvt.u32.u64 %0, t; }" : "=r"(a) : "l"(p));
    return a;
}
__device__ __forceinline__ void cp_async16(uint32_t saddr, const void* gaddr) {
    asm volatile("cp.async.cg.shared.global [%0], [%1], 16;" :: "r"(saddr), "l"(gaddr));
}
#define CP_COMMIT() asm volatile("cp.async.commit_group;" ::: "memory")
#define CP_WAIT(n)  asm volatile("cp.async.wait_group %0;" :: "n"(n) : "memory")

__device__ __forceinline__ void ldm_x4(uint32_t& r0, uint32_t& r1, uint32_t& r2, uint32_t& r3, uint32_t a) {
    asm volatile("ldmatrix.sync.aligned.m8n8.x4.shared.b16 {%0,%1,%2,%3}, [%4];"
                 : "=r"(r0), "=r"(r1), "=r"(r2), "=r"(r3) : "r"(a));
}
__device__ __forceinline__ void mma_f32(float* c, const uint32_t* a, const uint32_t* b) {
    asm volatile("mma.sync.aligned.m16n8k16.row.col.f32.f16.f16.f32 "
                 "{%0,%1,%2,%3}, {%4,%5,%6,%7}, {%8,%9}, {%0,%1,%2,%3};"
                 : "+f"(c[0]), "+f"(c[1]), "+f"(c[2]), "+f"(c[3])
                 : "r"(a[0]), "r"(a[1]), "r"(a[2]), "r"(a[3]), "r"(b[0]), "r"(b[1]));
}
__device__ __forceinline__ void mma_f16(uint32_t* c, const uint32_t* a, const uint32_t* b) {
    asm volatile("mma.sync.aligned.m16n8k16.row.col.f16.f16.f16.f16 "
                 "{%0,%1}, {%2,%3,%4,%5}, {%6,%7}, {%0,%1};"
                 : "+r"(c[0]), "+r"(c[1])
                 : "r"(a[0]), "r"(a[1]), "r"(a[2]), "r"(a[3]), "r"(b[0]), "r"(b[1]));
}
__device__ __forceinline__ void merge_f16acc(float* c, const uint32_t* cx) {
    float2 v0 = __half22float2(*reinterpret_cast<const __half2*>(&cx[0]));
    float2 v1 = __half22float2(*reinterpret_cast<const __half2*>(&cx[1]));
    c[0] += v0.x; c[1] += v0.y; c[2] += v1.x; c[3] += v1.y;
}
__device__ __forceinline__ float ex2f(float x) {
    float y; asm("ex2.approx.f32 %0, %1;" : "=f"(y) : "f"(x)); return y;
}
__device__ __forceinline__ uint32_t pack_h2(float x, float y) {
    uint32_t h;
    asm("cvt.rn.f16x2.f32 %0, %1, %2;" : "=r"(h) : "f"(y), "f"(x));
    return h;
}
__device__ __forceinline__ void split2h(float x, float y, uint32_t& hi2, uint32_t& lo2) {
    uint32_t h = pack_h2(x, y);
    float2 hf = __half22float2(*reinterpret_cast<__half2*>(&h));
    lo2 = pack_h2(x - hf.x, y - hf.y);
    hi2 = h;
}

#define Q_SCALE 0.18033688011112042f   /* 0.125 * log2(e), folded into q */

// ---------------------------------------------------------------------------
// split kernels
// ---------------------------------------------------------------------------
__global__ __launch_bounds__(256) void split_rows(
    const float* __restrict__ in, __half* __restrict__ hi,
    __half* __restrict__ lo, int n4)
{
    int i = blockIdx.x * blockDim.x + threadIdx.x;
    if (i >= n4) return;
    float4 v = ((const float4*)in)[i];
    uint32_t h0, l0, h1, l1;
    split2h(v.x, v.y, h0, l0);
    split2h(v.z, v.w, h1, l1);
    ((uint32_t*)hi)[2 * i + 0] = h0; ((uint32_t*)hi)[2 * i + 1] = h1;
    ((uint32_t*)lo)[2 * i + 0] = l0; ((uint32_t*)lo)[2 * i + 1] = l1;
}

__global__ __launch_bounds__(256) void split_transpose(
    const float* __restrict__ w, __half* __restrict__ th,
    __half* __restrict__ tl, int K, int N)
{
    __shared__ float tile[32][33];
    int n0 = blockIdx.x * 32, k0 = blockIdx.y * 32;
    int tx = threadIdx.x, ty = threadIdx.y;  // (32, 8)
#pragma unroll
    for (int r = 0; r < 32; r += 8)
        tile[ty + r][tx] = w[(size_t)(k0 + ty + r) * N + n0 + tx];
    __syncthreads();
#pragma unroll
    for (int r = 0; r < 32; r += 8) {
        float v = tile[tx][ty + r];
        __half h = __float2half_rn(v);
        th[(size_t)(n0 + ty + r) * K + k0 + tx] = h;
        tl[(size_t)(n0 + ty + r) * K + k0 + tx] = __float2half_rn(v - __half2float(h));
    }
}

// ---------------------------------------------------------------------------
// HMMA GEMM mainloop — R11 config (proven fastest): CTA = 128 thr, tile
// 128x64, warps 2x2 (64x32 each), KC=32, 2-stage cp.async, 3 CTAs/SM.
// ---------------------------------------------------------------------------
#define KC 32
#define TILE_A (128 * 80u)
#define TILE_BT (64 * 80u)
#define STAGE_B (2 * TILE_A + 2 * TILE_BT)   // 30720 B; 2 stages = 61440 B

#define GEMM_MAINLOOP(Ahi, Alo, Bhi, Blo, Kdim, cacc, cx, LOADAL, LOADBL, DOAL, DOBL)    \
    extern __shared__ __align__(16) char dsm[];                                          \
    const uint32_t sbase = smem_u32(dsm);                                                \
    const int tid = threadIdx.x;                                                         \
    const int lane = tid & 31, wid = tid >> 5;                                           \
    const int wm = (wid >> 1) * 64;                                                      \
    const int wn = (wid & 1) * 32;                                                       \
    float cacc[4][4][4];                                                                 \
    uint32_t cx[4][4][2];                                                                \
    _Pragma("unroll") for (int i = 0; i < 4; i++)                                        \
    _Pragma("unroll") for (int j = 0; j < 4; j++) {                                      \
        _Pragma("unroll") for (int e = 0; e < 4; e++) cacc[i][j][e] = 0.0f;              \
        cx[i][j][0] = 0u; cx[i][j][1] = 0u;                                              \
    }                                                                                    \
    const int lrow = tid >> 2;                                                           \
    const int lcu  = tid & 3;                                                            \
    auto load_chunk = [&](int stage, int k0) {                                           \
        const uint32_t st = sbase + (uint32_t)stage * STAGE_B;                           \
        _Pragma("unroll") for (int i = 0; i < 4; i++) {                                  \
            int row = lrow + i * 32;                                                     \
            cp_async16(st + (uint32_t)(row * 80 + lcu * 16),                             \
                       (Ahi) + (size_t)(bm + row) * Kdim + k0 + lcu * 8);                \
        }                                                                                \
        if (LOADAL) {                                                                    \
            _Pragma("unroll") for (int i = 0; i < 4; i++) {                              \
                int row = lrow + i * 32;                                                 \
                cp_async16(st + TILE_A + (uint32_t)(row * 80 + lcu * 16),                \
                           (Alo) + (size_t)(bm + row) * Kdim + k0 + lcu * 8);            \
            }                                                                            \
        }                                                                                \
        _Pragma("unroll") for (int i = 0; i < 2; i++) {                                  \
            int row = lrow + i * 32;                                                     \
            cp_async16(st + 2 * TILE_A + (uint32_t)(row * 80 + lcu * 16),                \
                       (Bhi) + (size_t)(bn + row) * Kdim + k0 + lcu * 8);                \
        }                                                                                \
        if (LOADBL) {                                                                    \
            _Pragma("unroll") for (int i = 0; i < 2; i++) {                              \
                int row = lrow + i * 32;                                                 \
                cp_async16(st + 2 * TILE_A + TILE_BT + (uint32_t)(row * 80 + lcu * 16),  \
                           (Blo) + (size_t)(bn + row) * Kdim + k0 + lcu * 8);            \
            }                                                                            \
        }                                                                                \
        CP_COMMIT();                                                                     \
    };                                                                                   \
    const uint32_t aoff  = (uint32_t)((lane & 15) * 80 + (lane >> 4) * 16);              \
    const uint32_t boff4 = (uint32_t)((lane & 7) * 80 + ((lane >> 3) & 1) * 16           \
                                      + (lane >> 4) * 640);                              \
    const int nchunk = Kdim / KC;                                                        \
    load_chunk(0, 0);                                                                    \
    for (int ch = 0; ch < nchunk; ch++) {                                                \
        if (ch + 1 < nchunk) { load_chunk((ch + 1) & 1, (ch + 1) * KC); CP_WAIT(1); }    \
        else                 { CP_WAIT(0); }                                             \
        __syncthreads();                                                                 \
        const uint32_t st = sbase + (uint32_t)(ch & 1) * STAGE_B;                        \
        const uint32_t sAhi = st + (uint32_t)(wm * 80);                                  \
        const uint32_t sAlo = st + TILE_A + (uint32_t)(wm * 80);                         \
        const uint32_t sBhi = st + 2 * TILE_A + (uint32_t)(wn * 80);                     \
        const uint32_t sBlo = st + 2 * TILE_A + TILE_BT + (uint32_t)(wn * 80);           \
        _Pragma("unroll") for (int kk = 0; kk < KC; kk += 16) {                          \
            uint32_t ah[4][4], al[4][4], bh[4][2], bl[4][2];                             \
            _Pragma("unroll") for (int mi = 0; mi < 4; mi++) {                           \
                uint32_t abase = (uint32_t)(mi * 16 * 80 + kk * 2) + aoff;               \
                ldm_x4(ah[mi][0], ah[mi][1], ah[mi][2], ah[mi][3], sAhi + abase);        \
                if (DOAL) ldm_x4(al[mi][0], al[mi][1], al[mi][2], al[mi][3], sAlo + abase);\
            }                                                                            \
            _Pragma("unroll") for (int np = 0; np < 4; np += 2) {                        \
                uint32_t bbase = (uint32_t)(np * 8 * 80 + kk * 2) + boff4;               \
                ldm_x4(bh[np][0], bh[np][1], bh[np + 1][0], bh[np + 1][1], sBhi + bbase);\
                if (DOBL) ldm_x4(bl[np][0], bl[np][1], bl[np + 1][0], bl[np + 1][1], sBlo + bbase);\
            }                                                                            \
            _Pragma("unroll") for (int mi = 0; mi < 4; mi++)                             \
            _Pragma("unroll") for (int ni = 0; ni < 4; ni++)                             \
                mma_f32(cacc[mi][ni], ah[mi], bh[ni]);                                   \
            if (DOBL) {                                                                  \
                _Pragma("unroll") for (int mi = 0; mi < 4; mi++)                         \
                _Pragma("unroll") for (int ni = 0; ni < 4; ni++)                         \
                    mma_f16(cx[mi][ni], ah[mi], bl[ni]);                                 \
            }                                                                            \
            if (DOAL) {                                                                  \
                _Pragma("unroll") for (int mi = 0; mi < 4; mi++)                         \
                _Pragma("unroll") for (int ni = 0; ni < 4; ni++)                         \
                    mma_f16(cx[mi][ni], al[mi], bh[ni]);                                 \
            }                                                                            \
        }                                                                                \
        __syncthreads();                                                                 \
    }                                                                                    \
    _Pragma("unroll") for (int mi = 0; mi < 4; mi++)                                     \
    _Pragma("unroll") for (int ni = 0; ni < 4; ni++)                                     \
        merge_f16acc(cacc[mi][ni], cx[mi][ni]);

// GEMM variant 1: output projection. A = fp16 O (hi only), B split. 2-pass.
__global__ __launch_bounds__(128, 3) void gemm_proj(
    const __half* __restrict__ Ahi,
    const __half* __restrict__ Bhi, const __half* __restrict__ Blo,
    float* __restrict__ C, int N, int K)
{
    const int bm = blockIdx.y * 128, bn = blockIdx.x * 64;
    GEMM_MAINLOOP(Ahi, Ahi, Bhi, Blo, K, c, cxx, false, true, false, true)
#pragma unroll
    for (int mi = 0; mi < 4; mi++) {
        const int r0 = bm + wm + mi * 16 + (lane >> 2);
#pragma unroll
        for (int ni = 0; ni < 4; ni++) {
            const int col = bn + wn + ni * 8 + (lane & 3) * 2;
            *(float2*)(C + (size_t)r0 * N + col)       = make_float2(c[mi][ni][0], c[mi][ni][1]);
            *(float2*)(C + (size_t)(r0 + 8) * N + col) = make_float2(c[mi][ni][2], c[mi][ni][3]);
        }
    }
}

// GEMM variant 2: qkv. Q tiles 3-pass (q split hi/lo); K tiles 2-pass; V 1-pass.
__global__ __launch_bounds__(128, 3) void gemm_qkv(
    const __half* __restrict__ Ahi, const __half* __restrict__ Alo,
    const __half* __restrict__ Bhi, const __half* __restrict__ Blo,
    __half* __restrict__ qkhi, __half* __restrict__ qklo,
    __half* __restrict__ vthi,
    int K, int L, int Dq)
{
    const int bm = blockIdx.y * 128, bn = blockIdx.x * 64;
    const int D2 = 2 * Dq;
    const bool doA = (bn < Dq);
    const bool doB = (bn < D2);
    GEMM_MAINLOOP(Ahi, Alo, Bhi, Blo, K, c, cxx, doA, doB, doA, doB)
#pragma unroll
    for (int mi = 0; mi < 4; mi++) {
#pragma unroll
        for (int ni = 0; ni < 4; ni++) {
            const int col = bn + wn + ni * 8 + (lane & 3) * 2;
            const float sc = (col < Dq) ? Q_SCALE : 1.0f;
#pragma unroll
            for (int half = 0; half < 2; half++) {
                const int row = bm + wm + mi * 16 + (lane >> 2) + half * 8;
                float x = c[mi][ni][2 * half] * sc, y = c[mi][ni][2 * half + 1] * sc;
                if (col < Dq) {                     // q: hi + lo
                    uint32_t hi2, lo2;
                    split2h(x, y, hi2, lo2);
                    *(uint32_t*)(qkhi + (size_t)row * D2 + col) = hi2;
                    *(uint32_t*)(qklo + (size_t)row * D2 + col) = lo2;
                } else if (col < D2) {              // k: hi only
                    *(uint32_t*)(qkhi + (size_t)row * D2 + col) = pack_h2(x, y);
                } else {                            // v: transposed fp16
                    uint32_t hi2 = pack_h2(x, y);
                    int cc = col - D2, hh = cc >> 6, dd = cc & 63;
                    int bb = row / L, ll = row % L;
                    size_t base = ((size_t)((bb * HEADS + hh) * 64 + dd)) * L + ll;
                    ((unsigned short*)vthi)[base]     = (unsigned short)(hi2 & 0xFFFF);
                    ((unsigned short*)vthi)[base + L] = (unsigned short)(hi2 >> 16);
                }
            }
        }
    }
}

// ---------------------------------------------------------------------------
// Tensor-core flash attention (causal). R13 structure (smem Q-lo, 3 CTAs/SM,
// regs ~164) with ONE barrier per tile in the CORRECT order:
//   CP_WAIT -> __syncthreads -> loadKV(t+2) -> compute(t)
// (wait precedes barrier => all threads' stage-t copies are visible; the
// stage overwritten by loadKV(t+2) was last read in compute(t-1), before
// this barrier). Mask branch unswitched.
// ---------------------------------------------------------------------------
#define KSTR 144u
#define ATT_STG 18432u
#define QLO_B 9216u

__global__ __launch_bounds__(128, 3) void attn_mma(
    const __half* __restrict__ qkhi, const __half* __restrict__ qklo,
    const __half* __restrict__ vthi,
    __half* __restrict__ aohi,
    int L, int Dq)
{
    extern __shared__ __align__(16) char dsm[];
    const uint32_t sb = smem_u32(dsm);          // Q-lo region
    const uint32_t stg = sb + QLO_B;            // KV stage ring base
    const int h = blockIdx.y, b = blockIdx.z;
    const int qblk = gridDim.x - 1 - blockIdx.x;     // heavy first
    const int qlo = qblk * 64;
    const int tid = threadIdx.x, lane = tid & 31, w = tid >> 5;
    const int D2 = 2 * Dq;

    // ---- Q tile: hi -> stage0 (transient), lo -> persistent QLO region ----
#pragma unroll
    for (int i = 0; i < 8; i++) {
        int idx = tid + i * 128;
        int arr = idx >> 9;                      // 0 = Q-hi, 1 = Q-lo
        int r = (idx >> 3) & 63;
        int u = idx & 7;
        const __half* g = (arr ? qklo : qkhi) +
            (size_t)(b * L + qlo + r) * D2 + h * HEAD_DIM + u * 8;
        uint32_t dst = (arr ? sb : stg) + (uint32_t)r * KSTR + u * 16;
        cp_async16(dst, g);
    }
    CP_COMMIT();
    CP_WAIT(0);
    __syncthreads();

    uint32_t aQh[4][4];
    const uint32_t aoff = (uint32_t)((lane & 15) * KSTR + (lane >> 4) * 16);
#pragma unroll
    for (int g = 0; g < 4; g++) {
        uint32_t base = stg + (uint32_t)(w * 16) * KSTR + g * 32 + aoff;
        ldm_x4(aQh[g][0], aQh[g][1], aQh[g][2], aQh[g][3], base);
    }
    __syncthreads();   // Q-hi consumed; stage0 free. Q-lo stays in smem.
    const uint32_t qlbase = sb + (uint32_t)(w * 16) * KSTR + aoff;

    float cO[8][4];
#pragma unroll
    for (int n = 0; n < 8; n++)
#pragma unroll
        for (int e = 0; e < 4; e++) cO[n][e] = 0.0f;
    float m0 = -1e30f, m1 = -1e30f, ls0 = 0.0f, ls1 = 0.0f;

    const int nt = qblk + 1;
    auto loadKV = [&](int s, int kb) {
        const uint32_t st = stg + (uint32_t)s * ATT_STG;
#pragma unroll
        for (int i = 0; i < 8; i++) {
            int idx = tid + i * 128;
            int arr = idx >> 9;                  // 0 = K-hi, 1 = V-hi
            int r = (idx >> 3) & 63;
            int u = idx & 7;
            const __half* g;
            if (arr == 0)
                g = qkhi + (size_t)(b * L + kb + r) * D2 + Dq + h * HEAD_DIM + u * 8;
            else
                g = vthi + (size_t)((b * HEADS + h) * HEAD_DIM + r) * L + kb + u * 8;
            cp_async16(st + (uint32_t)arr * 9216u + (uint32_t)r * KSTR + u * 16, g);
        }
        CP_COMMIT();
    };

    loadKV(0, 0);
    if (nt > 1) loadKV(1, 64);
    const uint32_t boff4 = (uint32_t)((lane & 7) * KSTR + ((lane >> 3) & 1) * 16
                                      + (lane >> 4) * (8 * KSTR));
    const int r0 = qlo + w * 16 + (lane >> 2);
    const int colb = 2 * (lane & 3);

    for (int t = 0; t < nt; t++) {
        // Wait for stage t (own groups), THEN barrier (publishes all threads'
        // copies), THEN issue the next load into the stage freed at t-1.
        if (t + 1 < nt) CP_WAIT(1); else CP_WAIT(0);
        __syncthreads();
        if (t + 2 < nt) loadKV((t + 2) % 3, (t + 2) * 64);

        const int kb = t * 64;
        const uint32_t st = stg + (uint32_t)(t % 3) * ATT_STG;

        // ---- S = Q K^T: qh*kh f32 + ql*kh f16 (ql reloaded from smem) ----
        float cS[8][4];
        uint32_t cSx[8][2];
#pragma unroll
        for (int t8 = 0; t8 < 8; t8++) {
#pragma unroll
            for (int e = 0; e < 4; e++) cS[t8][e] = 0.0f;
            cSx[t8][0] = 0u; cSx[t8][1] = 0u;
        }
#pragma unroll
        for (int g = 0; g < 4; g++) {
            uint32_t ql[4];
            ldm_x4(ql[0], ql[1], ql[2], ql[3], qlbase + g * 32);
#pragma unroll
            for (int t8 = 0; t8 < 8; t8 += 2) {
                uint32_t kaddr = st + (uint32_t)(t8 * 8) * KSTR + g * 32 + boff4;
                uint32_t kh[4];
                ldm_x4(kh[0], kh[1], kh[2], kh[3], kaddr);
                mma_f32(cS[t8],     aQh[g], kh + 0);
                mma_f32(cS[t8 + 1], aQh[g], kh + 2);
                mma_f16(cSx[t8],     ql, kh + 0);
                mma_f16(cSx[t8 + 1], ql, kh + 2);
            }
        }
#pragma unroll
        for (int t8 = 0; t8 < 8; t8++) merge_f16acc(cS[t8], cSx[t8]);

        // ---- mask (unswitched) + online softmax (exp2 domain) ----
        const bool maskT = (kb + 63) > (qlo + w * 16);
        float mt0 = -1e30f, mt1 = -1e30f;
        if (maskT) {
#pragma unroll
            for (int t8 = 0; t8 < 8; t8++) {
                const int c0 = kb + 8 * t8 + colb;
#pragma unroll
                for (int e = 0; e < 4; e++) {
                    float s = cS[t8][e];
                    int col = c0 + (e & 1);
                    int row = (e < 2) ? r0 : (r0 + 8);
                    if (col > row) s = -1e30f;
                    cS[t8][e] = s;
                    if (e < 2) mt0 = fmaxf(mt0, s); else mt1 = fmaxf(mt1, s);
                }
            }
        } else {
#pragma unroll
            for (int t8 = 0; t8 < 8; t8++) {
                mt0 = fmaxf(mt0, fmaxf(cS[t8][0], cS[t8][1]));
                mt1 = fmaxf(mt1, fmaxf(cS[t8][2], cS[t8][3]));
            }
        }
        mt0 = fmaxf(mt0, __shfl_xor_sync(0xffffffffu, mt0, 1));
        mt0 = fmaxf(mt0, __shfl_xor_sync(0xffffffffu, mt0, 2));
        mt1 = fmaxf(mt1, __shfl_xor_sync(0xffffffffu, mt1, 1));
        mt1 = fmaxf(mt1, __shfl_xor_sync(0xffffffffu, mt1, 2));
        const float mn0 = fmaxf(m0, mt0), mn1 = fmaxf(m1, mt1);
        const float f0 = ex2f(m0 - mn0), f1 = ex2f(m1 - mn1);
        m0 = mn0; m1 = mn1;
        float ps0 = 0.0f, ps1 = 0.0f;
        uint32_t pk[8][2];
#pragma unroll
        for (int t8 = 0; t8 < 8; t8++) {
            float p0 = ex2f(cS[t8][0] - mn0);
            float p1 = ex2f(cS[t8][1] - mn0);
            float p2 = ex2f(cS[t8][2] - mn1);
            float p3 = ex2f(cS[t8][3] - mn1);
            ps0 += p0 + p1; ps1 += p2 + p3;
            pk[t8][0] = pack_h2(p0, p1);
            pk[t8][1] = pack_h2(p2, p3);
        }
        ls0 = ls0 * f0 + ps0;
        ls1 = ls1 * f1 + ps1;
#pragma unroll
        for (int n = 0; n < 8; n++) {
            cO[n][0] *= f0; cO[n][1] *= f0; cO[n][2] *= f1; cO[n][3] *= f1;
        }
        // ---- O += P V: single fp16 pass ----
#pragma unroll
        for (int g = 0; g < 4; g++) {
            uint32_t a[4] = { pk[2 * g][0], pk[2 * g][1], pk[2 * g + 1][0], pk[2 * g + 1][1] };
#pragma unroll
            for (int n = 0; n < 8; n += 2) {
                uint32_t vaddr = st + 9216u + (uint32_t)(n * 8) * KSTR + g * 32 + boff4;
                uint32_t vh[4];
                ldm_x4(vh[0], vh[1], vh[2], vh[3], vaddr);
                mma_f32(cO[n],     a, vh + 0);
                mma_f32(cO[n + 1], a, vh + 2);
            }
        }
    }

    // ---- epilogue: normalize, store fp16 ----
    float l0 = ls0;
    l0 += __shfl_xor_sync(0xffffffffu, l0, 1);
    l0 += __shfl_xor_sync(0xffffffffu, l0, 2);
    float l1 = ls1;
    l1 += __shfl_xor_sync(0xffffffffu, l1, 1);
    l1 += __shfl_xor_sync(0xffffffffu, l1, 2);
    const float i0 = 1.0f / l0, i1 = 1.0f / l1;

    const size_t o0 = (size_t)(b * L + r0) * Dq + h * HEAD_DIM;
    const size_t o1 = o0 + (size_t)8 * Dq;
#pragma unroll
    for (int n = 0; n < 8; n++) {
        *(uint32_t*)(aohi + o0 + n * 8 + colb) = pack_h2(cO[n][0] * i0, cO[n][1] * i0);
        *(uint32_t*)(aohi + o1 + n * 8 + colb) = pack_h2(cO[n][2] * i1, cO[n][3] * i1);
    }
}

// ---------------------------------------------------------------------------
// Launch
// ---------------------------------------------------------------------------
extern "C" void kernel_launch(void* const* d_in, const int* in_sizes, int n_in,
                              void* d_out, int out_size)
{
    const float* x      = (const float*)d_in[0];
    const float* w_qkv  = (const float*)d_in[1];
    const float* w_proj = (const float*)d_in[2];
    float* out = (float*)d_out;

    int D  = (int)(sqrt((double)in_sizes[2]) + 0.5);
    int BL = in_sizes[0] / D;
    int L  = 2048;
    if (BL < L) L = BL;
    int Bb = BL / L;

    __half *xhi, *xlo, *bhi, *blo, *qkhi, *qklo, *vthi, *aohi;
    cudaGetSymbolAddress((void**)&xhi, g_xhi);
    cudaGetSymbolAddress((void**)&xlo, g_xlo);
    cudaGetSymbolAddress((void**)&bhi, g_bhi);
    cudaGetSymbolAddress((void**)&blo, g_blo);
    cudaGetSymbolAddress((void**)&qkhi, g_qkhi);
    cudaGetSymbolAddress((void**)&qklo, g_qklo);
    cudaGetSymbolAddress((void**)&vthi, g_vthi);
    cudaGetSymbolAddress((void**)&aohi, g_aohi);

    const int gemmSmem = (int)(2 * STAGE_B);           // 61440 B -> 3 CTAs/SM
    const int attnSmem = (int)(QLO_B + 3 * ATT_STG);   // 64512 B -> 3 CTAs/SM
    cudaFuncSetAttribute(gemm_proj, cudaFuncAttributeMaxDynamicSharedMemorySize, gemmSmem);
    cudaFuncSetAttribute(gemm_qkv,  cudaFuncAttributeMaxDynamicSharedMemorySize, gemmSmem);
    cudaFuncSetAttribute(attn_mma,  cudaFuncAttributeMaxDynamicSharedMemorySize, attnSmem);

    // 1) qkv projection -> q(scaled) hi+lo, k hi, v transposed fp16
    split_rows<<<(BL * D / 4 + 255) / 256, 256>>>(x, xhi, xlo, BL * D / 4);
    split_transpose<<<dim3(3 * D / 32, D / 32), dim3(32, 8)>>>(w_qkv, bhi, blo, D, 3 * D);
    gemm_qkv<<<dim3(3 * D / 64, BL / 128), 128, gemmSmem>>>(
        xhi, xlo, bhi, blo, qkhi, qklo, vthi, D, L, D);

    // 2) tensor-core flash attention -> fp16 O
    attn_mma<<<dim3(L / 64, HEADS, Bb), 128, attnSmem>>>(
        qkhi, qklo, vthi, aohi, L, D);

    // 3) output projection (2-pass) -> fp32
    split_transpose<<<dim3(D / 32, D / 32), dim3(32, 8)>>>(w_proj, bhi, blo, D, D);
    gemm_proj<<<dim3(D / 64, BL / 128), 128, gemmSmem>>>(
        aohi, bhi, blo, out, D, D);
}